// round 1
// baseline (speedup 1.0000x reference)
#include <cuda_runtime.h>
#include <cstdint>

// Problem constants (fixed by the dataset)
#define BB   16
#define NN   4096
#define SS   1024
#define KK   32
#define DIN  64
#define DINC 67
#define DOUT 64

#define ROWS 128          // rows per block per phase-1 block
#define RP   132          // padded row-stride for transposed x tiles (mult of 4, avoids full STS conflicts)

// Scratch (static device globals: allocation-free per harness rules)
__device__ float g_sum[(size_t)BB * NN * DOUT];   // xc + bias (+ xp if use_x)
__device__ float g_xp [(size_t)BB * NN * DOUT];   // xp only (for center subtraction)
__device__ int   g_is64;                          // 1 if indexes are int64, 0 if int32

// ---------------------------------------------------------------------------
// Packed f32x2 helpers (FFMA2 is only reachable via PTX fma.rn.f32x2)
// ---------------------------------------------------------------------------
__device__ __forceinline__ void ffma2(unsigned long long& d, unsigned long long a, unsigned long long b) {
    asm volatile("fma.rn.f32x2 %0, %1, %2, %0;" : "+l"(d) : "l"(a), "l"(b));
}
__device__ __forceinline__ unsigned long long dup2(float x) {
    unsigned long long r;
    unsigned int xi = __float_as_uint(x);
    asm("mov.b64 %0, {%1, %1};" : "=l"(r) : "r"(xi));
    return r;
}
__device__ __forceinline__ float2 asf2(unsigned long long v) {
    float2 f;
    asm("mov.b64 {%0, %1}, %2;" : "=f"(f.x), "=f"(f.y) : "l"(v));
    return f;
}

// ---------------------------------------------------------------------------
// Kernel 0: detect whether indexes buffer is int64 or int32.
// int64 little-endian values in [-1, N): every odd 32-bit word must be the
// sign extension (0 or -1) of the preceding even word. Random int32 data in
// [-1, N) violates this with probability ~1 per pair.
// ---------------------------------------------------------------------------
__global__ void detect_kernel(const int* __restrict__ idx_words) {
    __shared__ int ok;
    if (threadIdx.x == 0) ok = 1;
    __syncthreads();
    for (int p = threadIdx.x; p < 2048; p += blockDim.x) {
        int lo = idx_words[2 * p];
        int hi = idx_words[2 * p + 1];
        int expect = (lo < 0) ? -1 : 0;
        if (hi != expect) ok = 0;   // benign race: only writes 0
    }
    __syncthreads();
    if (threadIdx.x == 0) g_is64 = ok;
}

// ---------------------------------------------------------------------------
// Kernel 1: fused dual projection.
//   g_xp [row] = x[row]          @ W2^T
//   g_sum[row] = x_complete[row] @ W1^T + bias (+ g_xp[row] if use_x)
// Block: 256 threads, handles 128 rows x 64 channels.
// Thread: 4 rows x 8 channels register tile, FFMA2 packed math.
// Shared: W1^T, W2^T (k-major), bias, transposed x tiles.
// ---------------------------------------------------------------------------
__global__ void __launch_bounds__(256, 2) proj_kernel(
    const float* __restrict__ x, const float* __restrict__ xcm,
    const float* __restrict__ w1, const float* __restrict__ w2,
    const float* __restrict__ bias, const int* __restrict__ use_x)
{
    extern __shared__ float sm[];
    float* sW1 = sm;                       // [67][64]  (k-major)
    float* sW2 = sW1 + DINC * DOUT;        // [64][64]
    float* sB  = sW2 + DIN  * DOUT;        // [64]
    float* sXC = sB  + 64;                 // [67][RP]  transposed x_complete tile
    float* sX  = sXC + DINC * RP;          // [64][RP]  transposed x tile

    const int tid = threadIdx.x;

    // Load weights transposed (one-time per block)
    for (int i = tid; i < DOUT * DINC; i += 256) {
        int c = i / DINC, k = i % DINC;
        sW1[k * DOUT + c] = w1[i];
    }
    for (int i = tid; i < DOUT * DIN; i += 256) {
        int c = i >> 6, k = i & 63;
        sW2[k * DOUT + c] = w2[i];
    }
    if (tid < DOUT) sB[tid] = bias[tid];
    const int ux = use_x[0];

    // Load this block's 128 rows, transposed into shared
    const size_t base = (size_t)blockIdx.x * ROWS;
    const float* xcg = xcm + base * DINC;
    const float* xg  = x   + base * DIN;
    for (int i = tid; i < ROWS * DINC; i += 256) {
        int r = i / DINC, k = i % DINC;
        sXC[k * RP + r] = xcg[i];
    }
    for (int i = tid; i < ROWS * DIN; i += 256) {
        int r = i >> 6, k = i & 63;
        sX[k * RP + r] = xg[i];
    }
    __syncthreads();

    const int cg = tid & 7;    // channel group (8 groups of 8 channels)
    const int rg = tid >> 3;   // row group (32 groups of 4 rows)
    const int c0 = cg * 8;
    const int r0 = rg * 4;

    unsigned long long acc1[4][4];  // W1 part (+bias): [row][f32x2 pair]
    // init acc1 with bias
    {
        const ulonglong2* bp = (const ulonglong2*)(sB + c0);
        ulonglong2 b01 = bp[0], b23 = bp[1];
        #pragma unroll
        for (int i = 0; i < 4; i++) {
            acc1[i][0] = b01.x; acc1[i][1] = b01.y;
            acc1[i][2] = b23.x; acc1[i][3] = b23.y;
        }
    }

    // xc @ W1^T
    #pragma unroll 2
    for (int k = 0; k < DINC; k++) {
        float4 xv = *(const float4*)(sXC + k * RP + r0);
        ulonglong2 wv0 = *(const ulonglong2*)(sW1 + k * DOUT + c0);
        ulonglong2 wv1 = *(const ulonglong2*)(sW1 + k * DOUT + c0 + 4);
        unsigned long long xs0 = dup2(xv.x), xs1 = dup2(xv.y), xs2 = dup2(xv.z), xs3 = dup2(xv.w);
        ffma2(acc1[0][0], xs0, wv0.x); ffma2(acc1[0][1], xs0, wv0.y); ffma2(acc1[0][2], xs0, wv1.x); ffma2(acc1[0][3], xs0, wv1.y);
        ffma2(acc1[1][0], xs1, wv0.x); ffma2(acc1[1][1], xs1, wv0.y); ffma2(acc1[1][2], xs1, wv1.x); ffma2(acc1[1][3], xs1, wv1.y);
        ffma2(acc1[2][0], xs2, wv0.x); ffma2(acc1[2][1], xs2, wv0.y); ffma2(acc1[2][2], xs2, wv1.x); ffma2(acc1[2][3], xs2, wv1.y);
        ffma2(acc1[3][0], xs3, wv0.x); ffma2(acc1[3][1], xs3, wv0.y); ffma2(acc1[3][2], xs3, wv1.x); ffma2(acc1[3][3], xs3, wv1.y);
    }

    unsigned long long accp[4][4];  // W2 part (xp)
    #pragma unroll
    for (int i = 0; i < 4; i++)
        accp[i][0] = accp[i][1] = accp[i][2] = accp[i][3] = 0ULL;

    // x @ W2^T
    #pragma unroll 2
    for (int k = 0; k < DIN; k++) {
        float4 xv = *(const float4*)(sX + k * RP + r0);
        ulonglong2 wv0 = *(const ulonglong2*)(sW2 + k * DOUT + c0);
        ulonglong2 wv1 = *(const ulonglong2*)(sW2 + k * DOUT + c0 + 4);
        unsigned long long xs0 = dup2(xv.x), xs1 = dup2(xv.y), xs2 = dup2(xv.z), xs3 = dup2(xv.w);
        ffma2(accp[0][0], xs0, wv0.x); ffma2(accp[0][1], xs0, wv0.y); ffma2(accp[0][2], xs0, wv1.x); ffma2(accp[0][3], xs0, wv1.y);
        ffma2(accp[1][0], xs1, wv0.x); ffma2(accp[1][1], xs1, wv0.y); ffma2(accp[1][2], xs1, wv1.x); ffma2(accp[1][3], xs1, wv1.y);
        ffma2(accp[2][0], xs2, wv0.x); ffma2(accp[2][1], xs2, wv0.y); ffma2(accp[2][2], xs2, wv1.x); ffma2(accp[2][3], xs2, wv1.y);
        ffma2(accp[3][0], xs3, wv0.x); ffma2(accp[3][1], xs3, wv0.y); ffma2(accp[3][2], xs3, wv1.x); ffma2(accp[3][3], xs3, wv1.y);
    }

    // Write xp and sum (coalesced: 8 adjacent threads cover 64 contiguous floats)
    #pragma unroll
    for (int i = 0; i < 4; i++) {
        size_t row = base + r0 + i;
        float2 p0 = asf2(accp[i][0]), p1 = asf2(accp[i][1]), p2 = asf2(accp[i][2]), p3 = asf2(accp[i][3]);
        float2 a0 = asf2(acc1[i][0]), a1 = asf2(acc1[i][1]), a2 = asf2(acc1[i][2]), a3 = asf2(acc1[i][3]);
        float4 pv0 = make_float4(p0.x, p0.y, p1.x, p1.y);
        float4 pv1 = make_float4(p2.x, p2.y, p3.x, p3.y);
        float4 sv0, sv1;
        if (ux) {
            sv0 = make_float4(a0.x + p0.x, a0.y + p0.y, a1.x + p1.x, a1.y + p1.y);
            sv1 = make_float4(a2.x + p2.x, a2.y + p2.y, a3.x + p3.x, a3.y + p3.y);
        } else {
            sv0 = make_float4(a0.x, a0.y, a1.x, a1.y);
            sv1 = make_float4(a2.x, a2.y, a3.x, a3.y);
        }
        float* po = g_xp  + row * DOUT + c0;
        float* so = g_sum + row * DOUT + c0;
        *(float4*)(po)     = pv0;
        *(float4*)(po + 4) = pv1;
        *(float4*)(so)     = sv0;
        *(float4*)(so + 4) = sv1;
    }
}

// ---------------------------------------------------------------------------
// Kernel 2: gather + masked max + center subtraction.
// One warp per (b, s). Lane l owns channels 2l, 2l+1 (float2).
//   out[b,s,:] = max over valid k of g_sum[b, idx_k, :]  -  (use_x ? g_xp[b, idx_0, :] : 0)
// (max commutes with subtracting the k-invariant center; masked slots sit at
//  ~ -1e10 in the reference and idx_0 is always valid, so skipping them is exact)
// ---------------------------------------------------------------------------
__global__ void __launch_bounds__(256) pool_kernel(
    const void* __restrict__ indexes, const int* __restrict__ use_x,
    float* __restrict__ out)
{
    const int w = (blockIdx.x * blockDim.x + threadIdx.x) >> 5;   // 0 .. B*S-1
    const int lane = threadIdx.x & 31;
    if (w >= BB * SS) return;
    const int b = w >> 10;   // w / SS

    int myi;
    if (g_is64) myi = (int)((const long long*)indexes)[(size_t)w * KK + lane];
    else        myi = ((const int*)indexes)[(size_t)w * KK + lane];

    const float* sumb = g_sum + (size_t)b * NN * DOUT;
    const int ux = use_x[0];

    const int id0 = __shfl_sync(0xffffffffu, myi, 0);   // always valid per dataset construction
    float2 cen = make_float2(0.f, 0.f);
    if (ux) {
        const float* xpb = g_xp + ((size_t)b * NN + id0) * DOUT;
        cen = *(const float2*)(xpb + 2 * lane);
    }

    float2 acc = make_float2(-3.4e38f, -3.4e38f);
    #pragma unroll 8
    for (int k = 0; k < KK; k++) {
        int id = __shfl_sync(0xffffffffu, myi, k);
        if (id >= 0) {
            float2 v = *(const float2*)(sumb + (size_t)id * DOUT + 2 * lane);
            acc.x = fmaxf(acc.x, v.x);
            acc.y = fmaxf(acc.y, v.y);
        }
    }

    float2 o = make_float2(acc.x - cen.x, acc.y - cen.y);
    *(float2*)(out + (size_t)w * DOUT + 2 * lane) = o;
}

// ---------------------------------------------------------------------------
// Launcher
// ---------------------------------------------------------------------------
extern "C" void kernel_launch(void* const* d_in, const int* in_sizes, int n_in,
                              void* d_out, int out_size)
{
    const float* x    = (const float*)d_in[0];
    const float* xcm  = (const float*)d_in[1];
    const void*  idx  = d_in[2];
    const float* w1   = (const float*)d_in[3];
    const float* w2   = (const float*)d_in[4];
    const float* bias = (const float*)d_in[5];
    const int*   ux   = (const int*)d_in[6];

    const int smem_bytes = (DINC * DOUT + DIN * DOUT + 64 + DINC * RP + DIN * RP) * 4; // 102960
    cudaFuncSetAttribute(proj_kernel, cudaFuncAttributeMaxDynamicSharedMemorySize, smem_bytes);

    detect_kernel<<<1, 256>>>((const int*)idx);
    proj_kernel<<<(BB * NN) / ROWS, 256, smem_bytes>>>(x, xcm, w1, w2, bias, ux);
    pool_kernel<<<(BB * SS * 32) / 256, 256>>>(idx, ux, (float*)d_out);
}

// round 2
// speedup vs baseline: 1.4831x; 1.4831x over previous
#include <cuda_runtime.h>
#include <cstdint>

// Problem constants (fixed by the dataset)
#define BB   16
#define NN   4096
#define SS   1024
#define KK   32
#define DIN  64
#define DINC 67
#define DOUT 64

#define ROWS 256          // rows per proj block
#define RP   258          // padded row-stride for transposed x tile (even, not mult of 4 in banks -> 2-way STS conflict)

// Scratch (static device globals: allocation-free per harness rules)
__device__ float g_sum[(size_t)BB * NN * DOUT];   // xc@W1 + bias (+ xp if use_x)
__device__ float g_xp [(size_t)BB * NN * DOUT];   // xp = x@W2 (center subtraction)

typedef unsigned long long ull;

// ---------------------------------------------------------------------------
// Packed f32x2 helpers
// ---------------------------------------------------------------------------
__device__ __forceinline__ void ffma2(ull& d, ull a, ull b) {
    asm volatile("fma.rn.f32x2 %0, %1, %2, %0;" : "+l"(d) : "l"(a), "l"(b));
}
__device__ __forceinline__ ull dup2(float x) {
    ull r;
    unsigned int xi = __float_as_uint(x);
    asm("mov.b64 %0, {%1, %1};" : "=l"(r) : "r"(xi));
    return r;
}
__device__ __forceinline__ float2 asf2(ull v) {
    float2 f;
    asm("mov.b64 {%0, %1}, %2;" : "=f"(f.x), "=f"(f.y) : "l"(v));
    return f;
}

// ---------------------------------------------------------------------------
// Proj kernel: 256 rows x 64 ch per block, 8x8 per-thread tile, row-paired FFMA2.
//   phase A (if use_x): acc  = x[rows] @ W2^T          -> write g_xp
//   phase B:            acc += xc[rows] @ W1^T (+bias) -> write g_sum
// Shared: W1^T, W2^T (k-major), bias, one transposed x tile (reused across phases).
// ---------------------------------------------------------------------------
__global__ void __launch_bounds__(256, 2) proj_kernel(
    const float* __restrict__ x, const float* __restrict__ xcm,
    const float* __restrict__ w1, const float* __restrict__ w2,
    const float* __restrict__ bias, const int* __restrict__ use_x)
{
    extern __shared__ float sm[];
    float* sW1 = sm;                       // [67][64]  k-major
    float* sW2 = sW1 + DINC * DOUT;        // [64][64]  k-major
    float* sB  = sW2 + DIN  * DOUT;        // [64]
    float* sXT = sB  + 64;                 // [67][RP]  transposed input tile (shared by both phases)

    const int tid = threadIdx.x;

    // Stage weights transposed (k-major) + bias
    for (int i = tid; i < DOUT * DINC; i += 256) {
        int c = i / DINC, k = i % DINC;
        sW1[k * DOUT + c] = w1[i];
    }
    for (int i = tid; i < DOUT * DIN; i += 256) {
        int c = i >> 6, k = i & 63;
        sW2[k * DOUT + c] = w2[i];
    }
    if (tid < DOUT) sB[tid] = bias[tid];
    const int ux = use_x[0];

    const size_t base = (size_t)blockIdx.x * ROWS;
    const int cg = tid & 7;     // 8 channel groups of 8
    const int rg = tid >> 3;    // 32 row groups of 8
    const int c0 = cg * 8;
    const int r0 = rg * 8;

    // Accumulators: 4 row-pairs x 8 channels (f32x2 packs rows 2i, 2i+1)
    ull acc[4][8];
    #pragma unroll
    for (int i = 0; i < 4; i++)
        #pragma unroll
        for (int c = 0; c < 8; c++) acc[i][c] = 0ULL;

    // ---------------- Phase A: xp = x @ W2^T (only when use_x) ----------------
    if (ux) {
        const float* xg = x + base * DIN;
        for (int i = tid; i < ROWS * DIN; i += 256) {
            int r = i >> 6, k = i & 63;
            sXT[k * RP + r] = xg[i];
        }
        __syncthreads();

        #pragma unroll 4
        for (int k = 0; k < DIN; k++) {
            const float* xr = sXT + k * RP + r0;
            ull x01 = *(const ull*)(xr);
            ull x23 = *(const ull*)(xr + 2);
            ull x45 = *(const ull*)(xr + 4);
            ull x67 = *(const ull*)(xr + 6);
            float4 wa = *(const float4*)(sW2 + k * DOUT + c0);
            float4 wb = *(const float4*)(sW2 + k * DOUT + c0 + 4);
            ull wd0 = dup2(wa.x), wd1 = dup2(wa.y), wd2 = dup2(wa.z), wd3 = dup2(wa.w);
            ull wd4 = dup2(wb.x), wd5 = dup2(wb.y), wd6 = dup2(wb.z), wd7 = dup2(wb.w);
            ffma2(acc[0][0], x01, wd0); ffma2(acc[0][1], x01, wd1); ffma2(acc[0][2], x01, wd2); ffma2(acc[0][3], x01, wd3);
            ffma2(acc[0][4], x01, wd4); ffma2(acc[0][5], x01, wd5); ffma2(acc[0][6], x01, wd6); ffma2(acc[0][7], x01, wd7);
            ffma2(acc[1][0], x23, wd0); ffma2(acc[1][1], x23, wd1); ffma2(acc[1][2], x23, wd2); ffma2(acc[1][3], x23, wd3);
            ffma2(acc[1][4], x23, wd4); ffma2(acc[1][5], x23, wd5); ffma2(acc[1][6], x23, wd6); ffma2(acc[1][7], x23, wd7);
            ffma2(acc[2][0], x45, wd0); ffma2(acc[2][1], x45, wd1); ffma2(acc[2][2], x45, wd2); ffma2(acc[2][3], x45, wd3);
            ffma2(acc[2][4], x45, wd4); ffma2(acc[2][5], x45, wd5); ffma2(acc[2][6], x45, wd6); ffma2(acc[2][7], x45, wd7);
            ffma2(acc[3][0], x67, wd0); ffma2(acc[3][1], x67, wd1); ffma2(acc[3][2], x67, wd2); ffma2(acc[3][3], x67, wd3);
            ffma2(acc[3][4], x67, wd4); ffma2(acc[3][5], x67, wd5); ffma2(acc[3][6], x67, wd6); ffma2(acc[3][7], x67, wd7);
        }

        // Write g_xp: per row, 64 contiguous channels per 8 threads -> coalesced
        #pragma unroll
        for (int rp = 0; rp < 4; rp++) {
            float2 f[8];
            #pragma unroll
            for (int c = 0; c < 8; c++) f[c] = asf2(acc[rp][c]);
            size_t rowA = base + r0 + 2 * rp;
            float* p0 = g_xp + rowA * DOUT + c0;
            float* p1 = p0 + DOUT;
            *(float4*)(p0)     = make_float4(f[0].x, f[1].x, f[2].x, f[3].x);
            *(float4*)(p0 + 4) = make_float4(f[4].x, f[5].x, f[6].x, f[7].x);
            *(float4*)(p1)     = make_float4(f[0].y, f[1].y, f[2].y, f[3].y);
            *(float4*)(p1 + 4) = make_float4(f[4].y, f[5].y, f[6].y, f[7].y);
        }
        __syncthreads();   // before overwriting the tile
    }

    // ---------------- Phase B: acc += xc @ W1^T ----------------
    {
        const float* xcg = xcm + base * DINC;
        for (int i = tid; i < ROWS * DINC; i += 256) {
            int r = i / DINC, k = i % DINC;
            sXT[k * RP + r] = xcg[i];
        }
        __syncthreads();

        #pragma unroll 4
        for (int k = 0; k < DINC; k++) {
            const float* xr = sXT + k * RP + r0;
            ull x01 = *(const ull*)(xr);
            ull x23 = *(const ull*)(xr + 2);
            ull x45 = *(const ull*)(xr + 4);
            ull x67 = *(const ull*)(xr + 6);
            float4 wa = *(const float4*)(sW1 + k * DOUT + c0);
            float4 wb = *(const float4*)(sW1 + k * DOUT + c0 + 4);
            ull wd0 = dup2(wa.x), wd1 = dup2(wa.y), wd2 = dup2(wa.z), wd3 = dup2(wa.w);
            ull wd4 = dup2(wb.x), wd5 = dup2(wb.y), wd6 = dup2(wb.z), wd7 = dup2(wb.w);
            ffma2(acc[0][0], x01, wd0); ffma2(acc[0][1], x01, wd1); ffma2(acc[0][2], x01, wd2); ffma2(acc[0][3], x01, wd3);
            ffma2(acc[0][4], x01, wd4); ffma2(acc[0][5], x01, wd5); ffma2(acc[0][6], x01, wd6); ffma2(acc[0][7], x01, wd7);
            ffma2(acc[1][0], x23, wd0); ffma2(acc[1][1], x23, wd1); ffma2(acc[1][2], x23, wd2); ffma2(acc[1][3], x23, wd3);
            ffma2(acc[1][4], x23, wd4); ffma2(acc[1][5], x23, wd5); ffma2(acc[1][6], x23, wd6); ffma2(acc[1][7], x23, wd7);
            ffma2(acc[2][0], x45, wd0); ffma2(acc[2][1], x45, wd1); ffma2(acc[2][2], x45, wd2); ffma2(acc[2][3], x45, wd3);
            ffma2(acc[2][4], x45, wd4); ffma2(acc[2][5], x45, wd5); ffma2(acc[2][6], x45, wd6); ffma2(acc[2][7], x45, wd7);
            ffma2(acc[3][0], x67, wd0); ffma2(acc[3][1], x67, wd1); ffma2(acc[3][2], x67, wd2); ffma2(acc[3][3], x67, wd3);
            ffma2(acc[3][4], x67, wd4); ffma2(acc[3][5], x67, wd5); ffma2(acc[3][6], x67, wd6); ffma2(acc[3][7], x67, wd7);
        }
    }

    // Write g_sum = acc + bias
    {
        float4 ba = *(const float4*)(sB + c0);
        float4 bb = *(const float4*)(sB + c0 + 4);
        #pragma unroll
        for (int rp = 0; rp < 4; rp++) {
            float2 f[8];
            #pragma unroll
            for (int c = 0; c < 8; c++) f[c] = asf2(acc[rp][c]);
            size_t rowA = base + r0 + 2 * rp;
            float* p0 = g_sum + rowA * DOUT + c0;
            float* p1 = p0 + DOUT;
            *(float4*)(p0)     = make_float4(f[0].x + ba.x, f[1].x + ba.y, f[2].x + ba.z, f[3].x + ba.w);
            *(float4*)(p0 + 4) = make_float4(f[4].x + bb.x, f[5].x + bb.y, f[6].x + bb.z, f[7].x + bb.w);
            *(float4*)(p1)     = make_float4(f[0].y + ba.x, f[1].y + ba.y, f[2].y + ba.z, f[3].y + ba.w);
            *(float4*)(p1 + 4) = make_float4(f[4].y + bb.x, f[5].y + bb.y, f[6].y + bb.z, f[7].y + bb.w);
        }
    }
}

// ---------------------------------------------------------------------------
// Pool kernel: one warp per (b,s). Lane l owns channels 2l, 2l+1.
// Inlined per-warp dtype detection (int64 vs int32 index buffer):
// reads 16 int64-candidate pairs from this warp's own int32-region (in-bounds
// under BOTH interpretations) and checks hi == sign-extension(lo).
// out[b,s,:] = max over valid k of g_sum[b,idx_k,:] - (ux ? g_xp[b,idx_0,:] : 0)
// ---------------------------------------------------------------------------
__global__ void __launch_bounds__(256) pool_kernel(
    const void* __restrict__ indexes, const int* __restrict__ use_x,
    float* __restrict__ out)
{
    const int w = (blockIdx.x * blockDim.x + threadIdx.x) >> 5;   // 0 .. B*S-1
    const int lane = threadIdx.x & 31;
    if (w >= BB * SS) return;
    const int b = w >> 10;

    // dtype detection (warp-local, deterministic for real data)
    int2 pr = ((const int2*)indexes)[(size_t)w * 16 + (lane & 15)];
    bool pok = (pr.y == (pr.x < 0 ? -1 : 0));
    bool is64 = __all_sync(0xffffffffu, pok);

    int myi;
    if (is64) myi = (int)((const long long*)indexes)[(size_t)w * KK + lane];
    else      myi = ((const int*)indexes)[(size_t)w * KK + lane];

    const float* sumb = g_sum + (size_t)b * NN * DOUT;
    const int ux = use_x[0];

    const int id0 = __shfl_sync(0xffffffffu, myi, 0);   // always valid by construction
    float2 cen = make_float2(0.f, 0.f);
    if (ux) {
        const float* xpb = g_xp + ((size_t)b * NN + id0) * DOUT;
        cen = *(const float2*)(xpb + 2 * lane);
    }

    // 4 independent max accumulators to break the fmax dependency chain
    float2 a0 = make_float2(-3.4e38f, -3.4e38f);
    float2 a1 = a0, a2 = a0, a3 = a0;
    #pragma unroll
    for (int k0 = 0; k0 < KK; k0 += 4) {
        int i0 = __shfl_sync(0xffffffffu, myi, k0 + 0);
        int i1 = __shfl_sync(0xffffffffu, myi, k0 + 1);
        int i2 = __shfl_sync(0xffffffffu, myi, k0 + 2);
        int i3 = __shfl_sync(0xffffffffu, myi, k0 + 3);
        if (i0 >= 0) { float2 v = *(const float2*)(sumb + (size_t)i0 * DOUT + 2 * lane); a0.x = fmaxf(a0.x, v.x); a0.y = fmaxf(a0.y, v.y); }
        if (i1 >= 0) { float2 v = *(const float2*)(sumb + (size_t)i1 * DOUT + 2 * lane); a1.x = fmaxf(a1.x, v.x); a1.y = fmaxf(a1.y, v.y); }
        if (i2 >= 0) { float2 v = *(const float2*)(sumb + (size_t)i2 * DOUT + 2 * lane); a2.x = fmaxf(a2.x, v.x); a2.y = fmaxf(a2.y, v.y); }
        if (i3 >= 0) { float2 v = *(const float2*)(sumb + (size_t)i3 * DOUT + 2 * lane); a3.x = fmaxf(a3.x, v.x); a3.y = fmaxf(a3.y, v.y); }
    }
    a0.x = fmaxf(fmaxf(a0.x, a1.x), fmaxf(a2.x, a3.x));
    a0.y = fmaxf(fmaxf(a0.y, a1.y), fmaxf(a2.y, a3.y));

    float2 o = make_float2(a0.x - cen.x, a0.y - cen.y);
    *(float2*)(out + (size_t)w * DOUT + 2 * lane) = o;
}

// ---------------------------------------------------------------------------
// Launcher
// ---------------------------------------------------------------------------
extern "C" void kernel_launch(void* const* d_in, const int* in_sizes, int n_in,
                              void* d_out, int out_size)
{
    const float* x    = (const float*)d_in[0];
    const float* xcm  = (const float*)d_in[1];
    const void*  idx  = d_in[2];
    const float* w1   = (const float*)d_in[3];
    const float* w2   = (const float*)d_in[4];
    const float* bias = (const float*)d_in[5];
    const int*   ux   = (const int*)d_in[6];

    const int smem_bytes = (DINC * DOUT + DIN * DOUT + 64 + DINC * RP) * 4;   // 102,936 B
    cudaFuncSetAttribute(proj_kernel, cudaFuncAttributeMaxDynamicSharedMemorySize, smem_bytes);

    proj_kernel<<<(BB * NN) / ROWS, 256, smem_bytes>>>(x, xcm, w1, w2, bias, ux);
    pool_kernel<<<(BB * SS * 32) / 256, 256>>>(idx, ux, (float*)d_out);
}

// round 3
// speedup vs baseline: 1.5103x; 1.0183x over previous
#include <cuda_runtime.h>
#include <cstdint>

// Problem constants (fixed by the dataset)
#define BB   16
#define NN   4096
#define SS   1024
#define KK   32
#define DIN  64
#define DINC 67
#define DOUT 64

#define ROWS 256          // rows per proj block
#define RP   258          // padded row-stride for transposed x tile (2-way STS conflict only)

// Scratch (static device globals: allocation-free per harness rules)
__device__ float g_sum[(size_t)BB * NN * DOUT];   // xc@W1 + bias (+ xp if use_x)
__device__ float g_xp [(size_t)BB * NN * DOUT];   // xp = x@W2 (center subtraction)

typedef unsigned long long ull;

// ---------------------------------------------------------------------------
// Packed f32x2 helpers
// ---------------------------------------------------------------------------
__device__ __forceinline__ void ffma2(ull& d, ull a, ull b) {
    asm("fma.rn.f32x2 %0, %1, %2, %0;" : "+l"(d) : "l"(a), "l"(b));
}
__device__ __forceinline__ ull dup2(float x) {
    ull r;
    unsigned int xi = __float_as_uint(x);
    asm("mov.b64 %0, {%1, %1};" : "=l"(r) : "r"(xi));
    return r;
}
__device__ __forceinline__ float2 asf2(ull v) {
    float2 f;
    asm("mov.b64 {%0, %1}, %2;" : "=f"(f.x), "=f"(f.y) : "l"(v));
    return f;
}

// ---------------------------------------------------------------------------
// Proj kernel (unchanged structure; at its FFMA ceiling):
//   phase A (if use_x): acc  = x[rows] @ W2^T          -> write g_xp
//   phase B:            acc += xc[rows] @ W1^T (+bias) -> write g_sum
// ---------------------------------------------------------------------------
__global__ void __launch_bounds__(256, 2) proj_kernel(
    const float* __restrict__ x, const float* __restrict__ xcm,
    const float* __restrict__ w1, const float* __restrict__ w2,
    const float* __restrict__ bias, const int* __restrict__ use_x)
{
    extern __shared__ float sm[];
    float* sW1 = sm;                       // [67][64]  k-major
    float* sW2 = sW1 + DINC * DOUT;        // [64][64]  k-major
    float* sB  = sW2 + DIN  * DOUT;        // [64]
    float* sXT = sB  + 64;                 // [67][RP]  transposed input tile

    const int tid = threadIdx.x;

    for (int i = tid; i < DOUT * DINC; i += 256) {
        int c = i / DINC, k = i % DINC;
        sW1[k * DOUT + c] = w1[i];
    }
    for (int i = tid; i < DOUT * DIN; i += 256) {
        int c = i >> 6, k = i & 63;
        sW2[k * DOUT + c] = w2[i];
    }
    if (tid < DOUT) sB[tid] = bias[tid];
    const int ux = use_x[0];

    const size_t base = (size_t)blockIdx.x * ROWS;
    const int cg = tid & 7;
    const int rg = tid >> 3;
    const int c0 = cg * 8;
    const int r0 = rg * 8;

    ull acc[4][8];
    #pragma unroll
    for (int i = 0; i < 4; i++)
        #pragma unroll
        for (int c = 0; c < 8; c++) acc[i][c] = 0ULL;

    // ---------------- Phase A: xp = x @ W2^T ----------------
    if (ux) {
        const float* xg = x + base * DIN;
        for (int i = tid; i < ROWS * DIN; i += 256) {
            int r = i >> 6, k = i & 63;
            sXT[k * RP + r] = xg[i];
        }
        __syncthreads();

        #pragma unroll 4
        for (int k = 0; k < DIN; k++) {
            const float* xr = sXT + k * RP + r0;
            ull x01 = *(const ull*)(xr);
            ull x23 = *(const ull*)(xr + 2);
            ull x45 = *(const ull*)(xr + 4);
            ull x67 = *(const ull*)(xr + 6);
            float4 wa = *(const float4*)(sW2 + k * DOUT + c0);
            float4 wb = *(const float4*)(sW2 + k * DOUT + c0 + 4);
            ull wd0 = dup2(wa.x), wd1 = dup2(wa.y), wd2 = dup2(wa.z), wd3 = dup2(wa.w);
            ull wd4 = dup2(wb.x), wd5 = dup2(wb.y), wd6 = dup2(wb.z), wd7 = dup2(wb.w);
            ffma2(acc[0][0], x01, wd0); ffma2(acc[0][1], x01, wd1); ffma2(acc[0][2], x01, wd2); ffma2(acc[0][3], x01, wd3);
            ffma2(acc[0][4], x01, wd4); ffma2(acc[0][5], x01, wd5); ffma2(acc[0][6], x01, wd6); ffma2(acc[0][7], x01, wd7);
            ffma2(acc[1][0], x23, wd0); ffma2(acc[1][1], x23, wd1); ffma2(acc[1][2], x23, wd2); ffma2(acc[1][3], x23, wd3);
            ffma2(acc[1][4], x23, wd4); ffma2(acc[1][5], x23, wd5); ffma2(acc[1][6], x23, wd6); ffma2(acc[1][7], x23, wd7);
            ffma2(acc[2][0], x45, wd0); ffma2(acc[2][1], x45, wd1); ffma2(acc[2][2], x45, wd2); ffma2(acc[2][3], x45, wd3);
            ffma2(acc[2][4], x45, wd4); ffma2(acc[2][5], x45, wd5); ffma2(acc[2][6], x45, wd6); ffma2(acc[2][7], x45, wd7);
            ffma2(acc[3][0], x67, wd0); ffma2(acc[3][1], x67, wd1); ffma2(acc[3][2], x67, wd2); ffma2(acc[3][3], x67, wd3);
            ffma2(acc[3][4], x67, wd4); ffma2(acc[3][5], x67, wd5); ffma2(acc[3][6], x67, wd6); ffma2(acc[3][7], x67, wd7);
        }

        #pragma unroll
        for (int rp = 0; rp < 4; rp++) {
            float2 f[8];
            #pragma unroll
            for (int c = 0; c < 8; c++) f[c] = asf2(acc[rp][c]);
            size_t rowA = base + r0 + 2 * rp;
            float* p0 = g_xp + rowA * DOUT + c0;
            float* p1 = p0 + DOUT;
            *(float4*)(p0)     = make_float4(f[0].x, f[1].x, f[2].x, f[3].x);
            *(float4*)(p0 + 4) = make_float4(f[4].x, f[5].x, f[6].x, f[7].x);
            *(float4*)(p1)     = make_float4(f[0].y, f[1].y, f[2].y, f[3].y);
            *(float4*)(p1 + 4) = make_float4(f[4].y, f[5].y, f[6].y, f[7].y);
        }
        __syncthreads();
    }

    // ---------------- Phase B: acc += xc @ W1^T ----------------
    {
        const float* xcg = xcm + base * DINC;
        for (int i = tid; i < ROWS * DINC; i += 256) {
            int r = i / DINC, k = i % DINC;
            sXT[k * RP + r] = xcg[i];
        }
        __syncthreads();

        #pragma unroll 4
        for (int k = 0; k < DINC; k++) {
            const float* xr = sXT + k * RP + r0;
            ull x01 = *(const ull*)(xr);
            ull x23 = *(const ull*)(xr + 2);
            ull x45 = *(const ull*)(xr + 4);
            ull x67 = *(const ull*)(xr + 6);
            float4 wa = *(const float4*)(sW1 + k * DOUT + c0);
            float4 wb = *(const float4*)(sW1 + k * DOUT + c0 + 4);
            ull wd0 = dup2(wa.x), wd1 = dup2(wa.y), wd2 = dup2(wa.z), wd3 = dup2(wa.w);
            ull wd4 = dup2(wb.x), wd5 = dup2(wb.y), wd6 = dup2(wb.z), wd7 = dup2(wb.w);
            ffma2(acc[0][0], x01, wd0); ffma2(acc[0][1], x01, wd1); ffma2(acc[0][2], x01, wd2); ffma2(acc[0][3], x01, wd3);
            ffma2(acc[0][4], x01, wd4); ffma2(acc[0][5], x01, wd5); ffma2(acc[0][6], x01, wd6); ffma2(acc[0][7], x01, wd7);
            ffma2(acc[1][0], x23, wd0); ffma2(acc[1][1], x23, wd1); ffma2(acc[1][2], x23, wd2); ffma2(acc[1][3], x23, wd3);
            ffma2(acc[1][4], x23, wd4); ffma2(acc[1][5], x23, wd5); ffma2(acc[1][6], x23, wd6); ffma2(acc[1][7], x23, wd7);
            ffma2(acc[2][0], x45, wd0); ffma2(acc[2][1], x45, wd1); ffma2(acc[2][2], x45, wd2); ffma2(acc[2][3], x45, wd3);
            ffma2(acc[2][4], x45, wd4); ffma2(acc[2][5], x45, wd5); ffma2(acc[2][6], x45, wd6); ffma2(acc[2][7], x45, wd7);
            ffma2(acc[3][0], x67, wd0); ffma2(acc[3][1], x67, wd1); ffma2(acc[3][2], x67, wd2); ffma2(acc[3][3], x67, wd3);
            ffma2(acc[3][4], x67, wd4); ffma2(acc[3][5], x67, wd5); ffma2(acc[3][6], x67, wd6); ffma2(acc[3][7], x67, wd7);
        }
    }

    {
        float4 ba = *(const float4*)(sB + c0);
        float4 bb = *(const float4*)(sB + c0 + 4);
        #pragma unroll
        for (int rp = 0; rp < 4; rp++) {
            float2 f[8];
            #pragma unroll
            for (int c = 0; c < 8; c++) f[c] = asf2(acc[rp][c]);
            size_t rowA = base + r0 + 2 * rp;
            float* p0 = g_sum + rowA * DOUT + c0;
            float* p1 = p0 + DOUT;
            *(float4*)(p0)     = make_float4(f[0].x + ba.x, f[1].x + ba.y, f[2].x + ba.z, f[3].x + ba.w);
            *(float4*)(p0 + 4) = make_float4(f[4].x + bb.x, f[5].x + bb.y, f[6].x + bb.z, f[7].x + bb.w);
            *(float4*)(p1)     = make_float4(f[0].y + ba.x, f[1].y + ba.y, f[2].y + ba.z, f[3].y + ba.w);
            *(float4*)(p1 + 4) = make_float4(f[4].y + bb.x, f[5].y + bb.y, f[6].y + bb.z, f[7].y + bb.w);
        }
    }
}

// ---------------------------------------------------------------------------
// Pool kernel v2.
// Block = 256 threads handles 16 (b,s) pairs; 16 threads per pair; lane owns
// 4 channels (float4 gathers).
//  * dtype detection (int32 vs int64 indexes) done block-wide from reads that
//    are in-bounds under BOTH interpretations; __syncthreads_and reduces.
//  * indices staged once to smem as int32; each 16-thread group reads its 32
//    indices via 8 broadcast LDS.128.
//  * padded idx (<0) clamped branchlessly to idx0 (always-valid center, whose
//    row already participates in the max -> result identical, no branches).
//  * 8 independent float4 max accumulators -> 32 LDG.128 in flight.
// ---------------------------------------------------------------------------
__global__ void __launch_bounds__(256) pool_kernel(
    const void* __restrict__ indexes, const int* __restrict__ use_x,
    float* __restrict__ out)
{
    __shared__ int sidx[512];           // 16 pairs x 32 idx
    const int tid = threadIdx.x;
    const size_t blk = blockIdx.x;      // 1024 blocks

    // Detection read: int2 over words [blk*512, blk*512+512) — exactly this
    // block's index region if int32; first half of it if int64. In-bounds
    // either way.
    int2 v = ((const int2*)indexes)[blk * 256 + tid];
    bool pok = (v.y == (v.x < 0 ? -1 : 0));
    int is64 = __syncthreads_and(pok);

    if (is64) {
        longlong2 q = ((const longlong2*)indexes)[blk * 256 + tid];
        sidx[2 * tid]     = (int)q.x;
        sidx[2 * tid + 1] = (int)q.y;
    } else {
        sidx[2 * tid]     = v.x;
        sidx[2 * tid + 1] = v.y;
    }
    __syncthreads();

    const int grp    = tid >> 4;                 // 0..15: pair group within block
    const int lane16 = tid & 15;                 // channel lane
    const size_t p   = blk * 16 + grp;           // global pair id, 0..16383
    const int b      = (int)(p >> 10);           // p / SS
    const int* myidx = sidx + grp * 32;

    const float* sumb = g_sum + (size_t)b * NN * DOUT;
    const int c0 = lane16 * 4;
    const int id0 = myidx[0];                    // always valid

    const int ux = use_x[0];
    float4 cen = make_float4(0.f, 0.f, 0.f, 0.f);
    if (ux)
        cen = *(const float4*)(g_xp + ((size_t)b * NN + id0) * DOUT + c0);

    float4 a[8];
    #pragma unroll
    for (int q = 0; q < 8; q++) a[q] = make_float4(-3.4e38f, -3.4e38f, -3.4e38f, -3.4e38f);

    #pragma unroll
    for (int q = 0; q < 8; q++) {
        int4 iq = ((const int4*)myidx)[q];       // broadcast LDS.128
        int j0 = iq.x < 0 ? id0 : iq.x;
        int j1 = iq.y < 0 ? id0 : iq.y;
        int j2 = iq.z < 0 ? id0 : iq.z;
        int j3 = iq.w < 0 ? id0 : iq.w;
        float4 v0 = *(const float4*)(sumb + (size_t)j0 * DOUT + c0);
        float4 v1 = *(const float4*)(sumb + (size_t)j1 * DOUT + c0);
        float4 v2 = *(const float4*)(sumb + (size_t)j2 * DOUT + c0);
        float4 v3 = *(const float4*)(sumb + (size_t)j3 * DOUT + c0);
        float4 m01, m23;
        m01.x = fmaxf(v0.x, v1.x); m01.y = fmaxf(v0.y, v1.y); m01.z = fmaxf(v0.z, v1.z); m01.w = fmaxf(v0.w, v1.w);
        m23.x = fmaxf(v2.x, v3.x); m23.y = fmaxf(v2.y, v3.y); m23.z = fmaxf(v2.z, v3.z); m23.w = fmaxf(v2.w, v3.w);
        a[q].x = fmaxf(m01.x, m23.x); a[q].y = fmaxf(m01.y, m23.y);
        a[q].z = fmaxf(m01.z, m23.z); a[q].w = fmaxf(m01.w, m23.w);
    }

    // tree-combine 8 accumulators
    #pragma unroll
    for (int st = 4; st > 0; st >>= 1)
        #pragma unroll
        for (int q = 0; q < st; q++) {
            a[q].x = fmaxf(a[q].x, a[q + st].x);
            a[q].y = fmaxf(a[q].y, a[q + st].y);
            a[q].z = fmaxf(a[q].z, a[q + st].z);
            a[q].w = fmaxf(a[q].w, a[q + st].w);
        }

    float4 o = make_float4(a[0].x - cen.x, a[0].y - cen.y, a[0].z - cen.z, a[0].w - cen.w);
    *(float4*)(out + p * DOUT + c0) = o;
}

// ---------------------------------------------------------------------------
// Launcher
// ---------------------------------------------------------------------------
extern "C" void kernel_launch(void* const* d_in, const int* in_sizes, int n_in,
                              void* d_out, int out_size)
{
    const float* x    = (const float*)d_in[0];
    const float* xcm  = (const float*)d_in[1];
    const void*  idx  = d_in[2];
    const float* w1   = (const float*)d_in[3];
    const float* w2   = (const float*)d_in[4];
    const float* bias = (const float*)d_in[5];
    const int*   ux   = (const int*)d_in[6];

    const int smem_bytes = (DINC * DOUT + DIN * DOUT + 64 + DINC * RP) * 4;   // 102,936 B
    cudaFuncSetAttribute(proj_kernel, cudaFuncAttributeMaxDynamicSharedMemorySize, smem_bytes);

    proj_kernel<<<(BB * NN) / ROWS, 256, smem_bytes>>>(x, xcm, w1, w2, bias, ux);
    pool_kernel<<<(BB * SS) / 16, 256>>>(idx, ux, (float*)d_out);
}